// round 17
// baseline (speedup 1.0000x reference)
#include <cuda_runtime.h>
#include <cuda_fp16.h>
#include <cstdint>

#define TSEQ   2048
#define DMODEL 1024
#define NHEADS 16
#define DKH    64
#define NBATCH 4
#define NROWS  (NBATCH * TSEQ)   // 8192

// fp16 scratch
__device__ __half g_qin[(size_t)NROWS * DMODEL];
__device__ __half g_kin[(size_t)NROWS * DMODEL];
__device__ __half g_vin[(size_t)NROWS * DMODEL];
__device__ __half g_wh[(size_t)4 * DMODEL * DMODEL];
__device__ __half g_q[(size_t)NROWS * DMODEL];
__device__ __half g_k[(size_t)NROWS * DMODEL];
__device__ __half g_vT[(size_t)NROWS * DMODEL];   // [bh][dim][t]
__device__ __half g_ctx[(size_t)NROWS * DMODEL];

// 0.125 (1/sqrt(dk)) * log2(e)
#define QSC 0.18033688f

// ---------------------------------------------------------------------------
static __device__ __forceinline__ void mma16816h(float* d, const uint32_t* a,
                                                 const uint32_t* b) {
    asm volatile(
        "mma.sync.aligned.m16n8k16.row.col.f32.f16.f16.f32 "
        "{%0,%1,%2,%3}, {%4,%5,%6,%7}, {%8,%9}, {%0,%1,%2,%3};"
        : "+f"(d[0]), "+f"(d[1]), "+f"(d[2]), "+f"(d[3])
        : "r"(a[0]), "r"(a[1]), "r"(a[2]), "r"(a[3]), "r"(b[0]), "r"(b[1]));
}

static __device__ __forceinline__ uint32_t packh2(float x, float y) {
    __half2 h = __floats2half2_rn(x, y);
    return *reinterpret_cast<uint32_t*>(&h);
}

static __device__ __forceinline__ uint32_t h2ex2(uint32_t x) {
    uint32_t r;
    asm("ex2.approx.f16x2 %0, %1;" : "=r"(r) : "r"(x));
    return r;
}

#define LDMX4(r, addr) \
    asm volatile("ldmatrix.sync.aligned.m8n8.x4.shared.b16 {%0,%1,%2,%3}, [%4];" \
        : "=r"((r)[0]), "=r"((r)[1]), "=r"((r)[2]), "=r"((r)[3]) : "r"(addr))
#define LDMX4T(r, addr) \
    asm volatile("ldmatrix.sync.aligned.m8n8.x4.trans.shared.b16 {%0,%1,%2,%3}, [%4];" \
        : "=r"((r)[0]), "=r"((r)[1]), "=r"((r)[2]), "=r"((r)[3]) : "r"(addr))

#define CP_ASYNC16(dst_u32, src_ptr) \
    asm volatile("cp.async.ca.shared.global [%0], [%1], 16;" :: "r"(dst_u32), "l"(src_ptr))
#define CP_COMMIT()   asm volatile("cp.async.commit_group;" ::: "memory")
#define CP_WAITG(n)   asm volatile("cp.async.wait_group %0;" :: "n"(n) : "memory")

// ---------------------------------------------------------------------------
// Single merged f32 -> f16 convert (one launch)
// ---------------------------------------------------------------------------
__global__ __launch_bounds__(256) void f2h_all(
    const float4* __restrict__ q, const float4* __restrict__ k,
    const float4* __restrict__ v, const float4* __restrict__ wq,
    const float4* __restrict__ wk, const float4* __restrict__ wv,
    const float4* __restrict__ wo,
    uint2* __restrict__ dq, uint2* __restrict__ dk, uint2* __restrict__ dv,
    uint2* __restrict__ dw, int nin4, int nw4)
{
    const int total = 3 * nin4 + 4 * nw4;
    for (int i = blockIdx.x * 256 + threadIdx.x; i < total; i += gridDim.x * 256) {
        float4 val;
        uint2* d;
        int off;
        if (i < 3 * nin4) {
            const int which = i / nin4, jo = i - which * nin4;
            const float4* s = (which == 0) ? q : (which == 1) ? k : v;
            d = (which == 0) ? dq : (which == 1) ? dk : dv;
            off = jo;
            val = s[jo];
        } else {
            const int j = i - 3 * nin4;
            const int which = j / nw4, jo = j - which * nw4;
            const float4* ws = (which == 0) ? wq : (which == 1) ? wk
                              : (which == 2) ? wv : wo;
            d = dw;
            off = j;
            val = ws[jo];
        }
        d[off] = make_uint2(packh2(val.x, val.y), packh2(val.z, val.w));
    }
}

// ---------------------------------------------------------------------------
// fp16 GEMM core: BK=32, 5-stage cp.async ring, fragment double-buffering.
// CTA 128x128 tile, 128 threads (4 warps), warp tile 64x64.
// sA rows 20 words/stage, sB k-rows 68 words/stage (proven conflict-free).
// Group/chunk invariant: chunk m's stage is committed at iter m-4 (or
// prologue); after this iter's commit, WAITG(2) => chunks <= c+2 resident.
// ---------------------------------------------------------------------------
#define AST 2560
#define BST 2176
#define NSTG 5
#define GSMEM (NSTG * (AST + BST) * 4)   // 94720 B

static __device__ __forceinline__ void gemm_body(
    const __half* __restrict__ A, const __half* __restrict__ W,
    const float* __restrict__ bias, void* __restrict__ Cv,
    int mode, float sc, uint32_t* smw)
{
    const int tid = threadIdx.x;                // 0..127
    const int lane = tid & 31, wid = tid >> 5;  // 4 warps
    const int warp_m = wid & 1, warp_n = wid >> 1;
    const int n0 = blockIdx.x * 128, m0 = blockIdx.y * 128;

    // cp.async loaders: 4 A-ops + 4 B-ops per thread per chunk
    const __half* Asrc[4];
    const __half* Bsrc[4];
    uint32_t a_dst[4], b_dst[4];
    const uint32_t smb = (uint32_t)__cvta_generic_to_shared(smw);
#pragma unroll
    for (int l = 0; l < 4; l++) {
        const int o = l * 128 + tid;
        const int arow = o >> 2, aseg = o & 3;
        Asrc[l] = A + (size_t)(m0 + arow) * DMODEL + 8 * aseg;
        a_dst[l] = smb + (arow * 20 + 4 * aseg) * 4;
        const int brow = o >> 4, bg = o & 15;
        Bsrc[l] = W + (size_t)brow * DMODEL + n0 + 8 * bg;
        b_dst[l] = smb + (NSTG * AST + brow * 68 + 4 * bg) * 4;
    }

    // ldmatrix addresses (stage 0, ks 0)
    const int lrow = (lane & 7) + ((lane >> 3) & 1) * 8;
    const int lsel = (lane >> 4) & 1;
    uint32_t a_addr0[4], b_addr0[4];
#pragma unroll
    for (int mi = 0; mi < 4; mi++)
        a_addr0[mi] = smb + (((warp_m * 64 + mi * 16 + lrow) * 20) + lsel * 4) * 4;
#pragma unroll
    for (int jp = 0; jp < 4; jp++)
        b_addr0[jp] = smb + (NSTG * AST + lrow * 68 + warp_n * 32 + jp * 8 + lsel * 4) * 4;

    float acc[4][8][4];
#pragma unroll
    for (int i = 0; i < 4; i++)
#pragma unroll
        for (int j = 0; j < 8; j++)
#pragma unroll
            for (int r = 0; r < 4; r++) acc[i][j][r] = 0.f;

    // prologue: stages 0..3 (chunks 0..3)
#pragma unroll
    for (int s = 0; s < 4; s++) {
#pragma unroll
        for (int l = 0; l < 4; l++) {
            CP_ASYNC16(a_dst[l] + s * AST * 4, Asrc[l] + s * 32);
            CP_ASYNC16(b_dst[l] + s * BST * 4, Bsrc[l] + (size_t)s * 32 * DMODEL);
        }
        CP_COMMIT();
    }
    CP_WAITG(3);        // chunk 0 resident
    __syncthreads();

    uint32_t afA[4][4], bfA[4][4];   // buffer A: current k-step frags
    uint32_t afB[4][4], bfB[4][4];   // buffer B: next k-step frags
    // preload (chunk 0, ks 0) -> A
#pragma unroll
    for (int mi = 0; mi < 4; mi++) LDMX4(afA[mi], a_addr0[mi]);
#pragma unroll
    for (int jp = 0; jp < 4; jp++) LDMX4T(bfA[jp], b_addr0[jp]);

    const int NC = DMODEL / 32;   // 32
    for (int c = 0; c < NC; ++c) {
        __syncthreads();   // all warps done with last iter's LDSMs
        if (c + 4 < NC) {  // fill stage (c+4)%5 with chunk c+4
            const int sl = (c + 4) % NSTG;
#pragma unroll
            for (int l = 0; l < 4; l++) {
                CP_ASYNC16(a_dst[l] + sl * AST * 4, Asrc[l] + (c + 4) * 32);
                CP_ASYNC16(b_dst[l] + sl * BST * 4,
                           Bsrc[l] + (size_t)(c + 4) * 32 * DMODEL);
            }
        }
        CP_COMMIT();

        const int st = c % NSTG;
        const uint32_t ao = st * AST * 4;
        const uint32_t bo = st * BST * 4;

        // LDSM (c, ks1) -> B while ks0 MMAs run
#pragma unroll
        for (int mi = 0; mi < 4; mi++) LDMX4(afB[mi], a_addr0[mi] + ao + 32);
#pragma unroll
        for (int jp = 0; jp < 4; jp++) LDMX4T(bfB[jp], b_addr0[jp] + bo + 4352);

        // MMA (c, ks0) from A
#pragma unroll
        for (int mi = 0; mi < 4; mi++)
#pragma unroll
            for (int j = 0; j < 8; j++)
                mma16816h(acc[mi][j], afA[mi], &bfA[j >> 1][(j & 1) * 2]);

        CP_WAITG(2);   // chunks <= c+2 resident -> chunk c+1 stage ready

        // LDSM (c+1, ks0) -> A while ks1 MMAs run
        if (c + 1 < NC) {
            const uint32_t ao1 = ((c + 1) % NSTG) * AST * 4;
            const uint32_t bo1 = ((c + 1) % NSTG) * BST * 4;
#pragma unroll
            for (int mi = 0; mi < 4; mi++) LDMX4(afA[mi], a_addr0[mi] + ao1);
#pragma unroll
            for (int jp = 0; jp < 4; jp++) LDMX4T(bfA[jp], b_addr0[jp] + bo1);
        }

        // MMA (c, ks1) from B
#pragma unroll
        for (int mi = 0; mi < 4; mi++)
#pragma unroll
            for (int j = 0; j < 8; j++)
                mma16816h(acc[mi][j], afB[mi], &bfB[j >> 1][(j & 1) * 2]);
    }

    // Epilogue
#pragma unroll
    for (int mi = 0; mi < 4; mi++) {
#pragma unroll
        for (int j = 0; j < 8; j++) {
            const int n = n0 + warp_n * 64 + j * 8 + 2 * (lane & 3);
            const float2 b2 = *(const float2*)(bias + n);
#pragma unroll
            for (int half = 0; half < 2; half++) {
                const int m = m0 + warp_m * 64 + mi * 16 + (lane >> 2) + half * 8;
                float vx = (acc[mi][j][half * 2 + 0] + b2.x) * sc;
                float vy = (acc[mi][j][half * 2 + 1] + b2.y) * sc;
                const int bb = m >> 11, t = m & (TSEQ - 1);
                const int h = n >> 6, dd = n & 63;
                if (mode == 1) {
                    __half* Ch = (__half*)Cv;
                    *(uint32_t*)&Ch[(((size_t)(bb * NHEADS + h) * TSEQ + t) << 6) + dd] =
                        packh2(vx, vy);
                } else if (mode == 2) {
                    __half* Ch = (__half*)Cv;
                    Ch[((size_t)(bb * NHEADS + h) * DKH + dd) * TSEQ + t]     = __float2half(vx);
                    Ch[((size_t)(bb * NHEADS + h) * DKH + dd + 1) * TSEQ + t] = __float2half(vy);
                } else {
                    float* Cf = (float*)Cv;
                    *(float2*)&Cf[(size_t)m * DMODEL + n] = make_float2(vx, vy);
                }
            }
        }
    }
}

__global__ __launch_bounds__(128, 2) void gemm_qkv(
    const __half* __restrict__ A0, const __half* __restrict__ A1,
    const __half* __restrict__ A2, const __half* __restrict__ W,
    const float* __restrict__ b0, const float* __restrict__ b1,
    const float* __restrict__ b2, __half* __restrict__ C0,
    __half* __restrict__ C1, __half* __restrict__ C2)
{
    extern __shared__ uint32_t smw[];
    const int z = blockIdx.z;
    const __half* A = (z == 0) ? A0 : ((z == 1) ? A1 : A2);
    const float* bias = (z == 0) ? b0 : ((z == 1) ? b1 : b2);
    void* C = (z == 0) ? (void*)C0 : ((z == 1) ? (void*)C1 : (void*)C2);
    const float sc = (z == 0) ? QSC : 1.0f;
    const int mode = (z == 2) ? 2 : 1;
    gemm_body(A, W + (size_t)z * DMODEL * DMODEL, bias, C, mode, sc, smw);
}

__global__ __launch_bounds__(128, 2) void gemm_out(
    const __half* __restrict__ A, const __half* __restrict__ W,
    const float* __restrict__ bias, float* __restrict__ C)
{
    extern __shared__ uint32_t smw[];
    gemm_body(A, W, bias, C, 0, 1.0f, smw);
}

// ---------------------------------------------------------------------------
// Flash attention (round-15 proven, frozen)
// ---------------------------------------------------------------------------
#define W36 36
#define KOFF 4608
#define VOFF 9216
#define STG  2304
#define ATTN_SMEM (13824 * 4)
#define ONES2 0x3C003C00u

__global__ __launch_bounds__(128, 2) void attn_mma(
    const __half* __restrict__ Q, const __half* __restrict__ K,
    const __half* __restrict__ VT, __half* __restrict__ ctx)
{
    extern __shared__ uint32_t smw[];

    const int tid = threadIdx.x, lane = tid & 31, wid = tid >> 5;
    const int bh = blockIdx.y;
    const int q0 = blockIdx.x * 128;

    const __half* Qg = Q  + (size_t)bh * TSEQ * DKH;
    const __half* Kg = K  + (size_t)bh * TSEQ * DKH;
    const __half* Vg = VT + (size_t)bh * DKH * TSEQ;

    for (int idx = tid; idx < 1024; idx += 128) {
        const int m = idx >> 3, g = idx & 7;
        uint4 u = *(const uint4*)(Qg + (size_t)(q0 + m) * DKH + 8 * g);
        *(uint4*)&smw[m * W36 + 4 * g] = u;
    }

    for (int idx = tid; idx < 512; idx += 128) {
        const int r = idx >> 3, g = idx & 7;
        CP_ASYNC16((uint32_t)__cvta_generic_to_shared(&smw[KOFF + r * W36 + 4 * g]),
                   Kg + (size_t)r * DKH + 8 * g);
        CP_ASYNC16((uint32_t)__cvta_generic_to_shared(&smw[VOFF + r * W36 + 4 * g]),
                   Vg + (size_t)r * TSEQ + 8 * g);
    }
    CP_COMMIT();

    const uint32_t smb = (uint32_t)__cvta_generic_to_shared(smw);
    const int lrow = (lane & 7) + ((lane >> 3) & 1) * 8;
    const int lsel = (lane >> 4) & 1;
    const int g4 = lane >> 3;
    const int bv_row = 8 * (g4 >> 1) + (lane & 7);
    const int bv_kh  = g4 & 1;

    __syncthreads();
    uint32_t qf[2][4][4];
#pragma unroll
    for (int qb = 0; qb < 2; qb++)
#pragma unroll
        for (int ks = 0; ks < 4; ks++)
            LDMX4(qf[qb][ks],
                  smb + (((64 * qb + 16 * wid + lrow) * W36) + 8 * ks + 4 * lsel) * 4);

    const uint32_t onesb[2] = {ONES2, ONES2};
    float acc_l[2][4];
    float acc_o[2][8][4];
#pragma unroll
    for (int qb = 0; qb < 2; qb++) {
#pragma unroll
        for (int r = 0; r < 4; r++) acc_l[qb][r] = 0.f;
#pragma unroll
        for (int j = 0; j < 8; j++)
#pragma unroll
            for (int r = 0; r < 4; r++) acc_o[qb][j][r] = 0.f;
    }

    const int NT = TSEQ / 64;   // 32

    for (int kt = 0; kt < NT; kt++) {
        const int s = kt & 1;
        if (kt + 1 < NT) {
            for (int idx = tid; idx < 512; idx += 128) {
                const int r = idx >> 3, g = idx & 7;
                CP_ASYNC16((uint32_t)__cvta_generic_to_shared(
                               &smw[KOFF + (s ^ 1) * STG + r * W36 + 4 * g]),
                           Kg + (size_t)((kt + 1) * 64 + r) * DKH + 8 * g);
                CP_ASYNC16((uint32_t)__cvta_generic_to_shared(
                               &smw[VOFF + (s ^ 1) * STG + r * W36 + 4 * g]),
                           Vg + (size_t)r * TSEQ + (kt + 1) * 64 + 8 * g);
            }
            CP_COMMIT();
            CP_WAITG(1);
        } else {
            CP_WAITG(0);
        }
        __syncthreads();

        const uint32_t kbase = smb + (KOFF + s * STG) * 4;
        const uint32_t vbase = smb + (VOFF + s * STG) * 4;

        float acc[2][8][4];
#pragma unroll
        for (int qb = 0; qb < 2; qb++)
#pragma unroll
            for (int j = 0; j < 8; j++)
#pragma unroll
                for (int r = 0; r < 4; r++) acc[qb][j][r] = 0.f;

#pragma unroll
        for (int ks = 0; ks < 4; ks++) {
#pragma unroll
            for (int np = 0; np < 4; np++) {
                uint32_t kf[4];
                LDMX4(kf, kbase + (((16 * np + bv_row) * W36) + 8 * ks + 4 * bv_kh) * 4);
#pragma unroll
                for (int qb = 0; qb < 2; qb++) {
                    mma16816h(acc[qb][2 * np],     qf[qb][ks], &kf[0]);
                    mma16816h(acc[qb][2 * np + 1], qf[qb][ks], &kf[2]);
                }
            }
        }

        uint32_t pf[2][4][4];
#pragma unroll
        for (int qb = 0; qb < 2; qb++) {
#pragma unroll
            for (int ks = 0; ks < 4; ks++) {
                pf[qb][ks][0] = h2ex2(packh2(acc[qb][2 * ks][0],     acc[qb][2 * ks][1]));
                pf[qb][ks][1] = h2ex2(packh2(acc[qb][2 * ks][2],     acc[qb][2 * ks][3]));
                pf[qb][ks][2] = h2ex2(packh2(acc[qb][2 * ks + 1][0], acc[qb][2 * ks + 1][1]));
                pf[qb][ks][3] = h2ex2(packh2(acc[qb][2 * ks + 1][2], acc[qb][2 * ks + 1][3]));
            }
#pragma unroll
            for (int ks = 0; ks < 4; ks++)
                mma16816h(acc_l[qb], pf[qb][ks], onesb);
        }

#pragma unroll
        for (int ks = 0; ks < 4; ks++) {
#pragma unroll
            for (int np = 0; np < 4; np++) {
                uint32_t vf[4];
                LDMX4(vf, vbase + (((16 * np + bv_row) * W36) + 8 * ks + 4 * bv_kh) * 4);
#pragma unroll
                for (int qb = 0; qb < 2; qb++) {
                    mma16816h(acc_o[qb][2 * np],     pf[qb][ks], &vf[0]);
                    mma16816h(acc_o[qb][2 * np + 1], pf[qb][ks], &vf[2]);
                }
            }
        }
        __syncthreads();
    }

    const int bb = bh >> 4, h = bh & 15;
#pragma unroll
    for (int qb = 0; qb < 2; qb++) {
        const float inv0 = 1.f / acc_l[qb][0];
        const float inv1 = 1.f / acc_l[qb][2];
        const int t0 = q0 + 64 * qb + 16 * wid + (lane >> 2);
#pragma unroll
        for (int nd = 0; nd < 8; nd++) {
            const int dim = h * 64 + 8 * nd + 2 * (lane & 3);
            *(uint32_t*)&ctx[((size_t)(bb * TSEQ) + t0) * DMODEL + dim] =
                packh2(acc_o[qb][nd][0] * inv0, acc_o[qb][nd][1] * inv0);
            *(uint32_t*)&ctx[((size_t)(bb * TSEQ) + t0 + 8) * DMODEL + dim] =
                packh2(acc_o[qb][nd][2] * inv1, acc_o[qb][nd][3] * inv1);
        }
    }
}

// ---------------------------------------------------------------------------
extern "C" void kernel_launch(void* const* d_in, const int* in_sizes, int n_in,
                              void* d_out, int out_size)
{
    const float* query = (const float*)d_in[0];
    const float* key   = (const float*)d_in[1];
    const float* value = (const float*)d_in[2];
    const float* Wq = (const float*)d_in[3];
    const float* bq = (const float*)d_in[4];
    const float* Wk = (const float*)d_in[5];
    const float* bk = (const float*)d_in[6];
    const float* Wv = (const float*)d_in[7];
    const float* bv = (const float*)d_in[8];
    const float* Wo = (const float*)d_in[9];
    const float* bo = (const float*)d_in[10];
    float* out = (float*)d_out;

    __half *qin, *kin, *vin, *wh, *qp, *kp, *vtp, *cp;
    cudaGetSymbolAddress((void**)&qin, g_qin);
    cudaGetSymbolAddress((void**)&kin, g_kin);
    cudaGetSymbolAddress((void**)&vin, g_vin);
    cudaGetSymbolAddress((void**)&wh,  g_wh);
    cudaGetSymbolAddress((void**)&qp,  g_q);
    cudaGetSymbolAddress((void**)&kp,  g_k);
    cudaGetSymbolAddress((void**)&vtp, g_vT);
    cudaGetSymbolAddress((void**)&cp,  g_ctx);

    cudaFuncSetAttribute(attn_mma,
                         cudaFuncAttributeMaxDynamicSharedMemorySize, ATTN_SMEM);
    cudaFuncSetAttribute(gemm_qkv,
                         cudaFuncAttributeMaxDynamicSharedMemorySize, GSMEM);
    cudaFuncSetAttribute(gemm_out,
                         cudaFuncAttributeMaxDynamicSharedMemorySize, GSMEM);

    const int NIN4 = NROWS * DMODEL / 4;
    const int NW4  = DMODEL * DMODEL / 4;
    const size_t WSZ = (size_t)DMODEL * DMODEL;
    f2h_all<<<2048, 256>>>((const float4*)query, (const float4*)key,
                           (const float4*)value, (const float4*)Wq,
                           (const float4*)Wk, (const float4*)Wv,
                           (const float4*)Wo, (uint2*)qin, (uint2*)kin,
                           (uint2*)vin, (uint2*)wh, NIN4, NW4);

    gemm_qkv<<<dim3(DMODEL / 128, NROWS / 128, 3), 128, GSMEM>>>(
        qin, kin, vin, wh, bq, bk, bv, qp, kp, vtp);
    attn_mma<<<dim3(TSEQ / 128, NBATCH * NHEADS), 128, ATTN_SMEM>>>(qp, kp, vtp, cp);
    gemm_out<<<dim3(DMODEL / 128, NROWS / 128), 128, GSMEM>>>(
        cp, wh + 3 * WSZ, bo, out);
}